// round 9
// baseline (speedup 1.0000x reference)
#include <cuda_runtime.h>
#include <cuda_bf16.h>
#include <cstddef>
#include <cstdint>

// Problem constants
#define BB     128
#define TT     512
#define HALF_T 256
#define DD     512
#define NCLS   7
#define MROWS  (BB * HALF_T)   // 32768 rows fed to FFN / head

typedef unsigned long long ull;

// ---------------------------------------------------------------------------
// mma.sync / ldmatrix / cp.async helpers (baseline PTX, sm_100-safe)
// ---------------------------------------------------------------------------
__device__ __forceinline__ uint32_t smem_u32(const void* p) {
    uint32_t a;
    asm("{ .reg .u64 t; cvta.to.shared.u64 t, %1; cvt.u32.u64 %0, t; }"
        : "=r"(a) : "l"(p));
    return a;
}
__device__ __forceinline__ void ldsm4(uint32_t* r, uint32_t addr) {
    asm volatile("ldmatrix.sync.aligned.m8n8.x4.shared.b16 {%0,%1,%2,%3}, [%4];"
        : "=r"(r[0]), "=r"(r[1]), "=r"(r[2]), "=r"(r[3]) : "r"(addr));
}
__device__ __forceinline__ void mma_bf16(float* d, const uint32_t* a,
                                         uint32_t b0, uint32_t b1) {
    asm volatile("mma.sync.aligned.m16n8k16.row.col.f32.bf16.bf16.f32 "
        "{%0,%1,%2,%3}, {%4,%5,%6,%7}, {%8,%9}, {%0,%1,%2,%3};"
        : "+f"(d[0]), "+f"(d[1]), "+f"(d[2]), "+f"(d[3])
        : "r"(a[0]), "r"(a[1]), "r"(a[2]), "r"(a[3]), "r"(b0), "r"(b1));
}
__device__ __forceinline__ void cpasync16(uint32_t dst, const void* src) {
    asm volatile("cp.async.cg.shared.global [%0], [%1], 16;"
                 :: "r"(dst), "l"(src));
}
#define CP_COMMIT() asm volatile("cp.async.commit_group;" ::: "memory")

// ---------------------------------------------------------------------------
// Device scratch
// ---------------------------------------------------------------------------
__device__ float g_gx[MROWS * 1536];             // input projections (fp32)
__device__ float g_x3[MROWS * DD];               // FFN layer-3 output (fp32)
__device__ __nv_bfloat16 g_A0 [MROWS * 1024];    // x0 split planes (hi|lo)
__device__ __nv_bfloat16 g_e2 [MROWS * 1024];    // emotions split planes
__device__ __nv_bfloat16 g_x1b[MROWS * 1024];
__device__ __nv_bfloat16 g_x2b[MROWS * 1024];
__device__ __nv_bfloat16 g_Wih2[1536 * 1024];    // weight split planes
__device__ __nv_bfloat16 g_W12 [512 * 1024];
__device__ __nv_bfloat16 g_W22 [512 * 1024];
__device__ __nv_bfloat16 g_W32 [512 * 1024];
__device__ __nv_bfloat16 g_h2[2 * BB * 1024];    // GRU h as bf16 hi|lo planes
__device__ float g_Wc[NCLS * DD];
__device__ float g_s [NCLS];
__device__ float g_bc[NCLS];
__device__ unsigned g_ctr4[4 * 32];              // barrier counters, 128B apart

// ---------------------------------------------------------------------------
// Init: zero h planes buffer 0 + barrier counters (reset every graph replay)
// ---------------------------------------------------------------------------
__global__ void k_init() {
    int idx = blockIdx.x * 256 + threadIdx.x;   // 65536 threads
    if (idx < BB * 1024 / 2) {
        ((__nv_bfloat162*)g_h2)[idx] = __nv_bfloat162{__nv_bfloat16(0.f),
                                                      __nv_bfloat16(0.f)};
    }
    if (idx < 4) g_ctr4[idx * 32] = 0u;
}

// ---------------------------------------------------------------------------
// prep1/prep2: fold log_softmax + classifier head
// ---------------------------------------------------------------------------
__global__ void k_prep1(const float* __restrict__ W_half,
                        const float* __restrict__ W_out) {
    int idx = blockIdx.x * 256 + threadIdx.x;
    if (idx >= NCLS * DD) return;
    int n = idx / DD, k = idx % DD;
    float s = 0.0f;
    for (int j = 0; j < 256; j++)
        s += W_out[n * 256 + j] * W_half[j * DD + k];
    g_Wc[idx] = s;
}
__global__ void k_prep2(const float* __restrict__ W_out,
                        const float* __restrict__ b_half,
                        const float* __restrict__ b_out) {
    int tid = threadIdx.x;
    int w = tid >> 5, l = tid & 31;
    if (w < NCLS) {
        float s = 0.0f;
        #pragma unroll
        for (int i = 0; i < 16; i++) s += g_Wc[w * DD + i * 32 + l];
        #pragma unroll
        for (int off = 16; off > 0; off >>= 1)
            s += __shfl_xor_sync(0xffffffffu, s, off);
        if (l == 0) g_s[w] = s;
    }
    if (tid < NCLS) {
        float b = b_out[tid];
        for (int j = 0; j < 256; j++)
            b += W_out[tid * 256 + j] * b_half[j];
        g_bc[tid] = b;
    }
}

// ---------------------------------------------------------------------------
// k_split: fp32 [rows,512] -> bf16 hi/lo planes [rows,1024]
// ---------------------------------------------------------------------------
__global__ void k_split(const float* __restrict__ src,
                        __nv_bfloat16* __restrict__ dst,
                        int nrows, int perm) {
    int idx = blockIdx.x * 256 + threadIdx.x;
    if (idx >= nrows * 128) return;
    int r = idx >> 7, c4 = (idx & 127) << 2;
    size_t so = perm ? ((size_t)((r >> 8) * 512 + (r & 255)) * 512)
                     : ((size_t)r * 512);
    float4 v = *(const float4*)(src + so + c4);
    __nv_bfloat16 h[4], lo[4];
    float vv[4] = {v.x, v.y, v.z, v.w};
    #pragma unroll
    for (int i = 0; i < 4; i++) {
        h[i] = __float2bfloat16(vv[i]);
        lo[i] = __float2bfloat16(vv[i] - __bfloat162float(h[i]));
    }
    *(ull*)(dst + (size_t)r * 1024 + c4)       = *(ull*)h;
    *(ull*)(dst + (size_t)r * 1024 + 512 + c4) = *(ull*)lo;
}

// ---------------------------------------------------------------------------
// mma.sync bf16-split GEMM, 4-stage cp.async pipeline, ONE sync per chunk.
//   C[m,n] = act( sum_k A[m,k]*B[n,k] + bias[n] ),  K' = 1536 (3 segments).
// ---------------------------------------------------------------------------
#define ROWB 80          // padded smem row: 32 bf16 (64B) + 16B pad
#define BUFB (128 * ROWB)
#define NST  4
#define GEMM_SMEM (2 * NST * BUFB)   // 81920

__global__ void __launch_bounds__(256, 2)
k_mma_gemm(const __nv_bfloat16* __restrict__ A,
           const __nv_bfloat16* __restrict__ Bw,
           const float* __restrict__ bias,
           void* __restrict__ Cout,
           int Ntot, int n_tiles, int mode) {
    extern __shared__ __align__(16) char smc[];
    uint32_t sbase = smem_u32(smc);
    int tid = threadIdx.x, wid = tid >> 5, lane = tid & 31;
    int m0 = (blockIdx.x / n_tiles) << 7;
    int n0 = (blockIdx.x % n_tiles) << 7;

    int sr = tid >> 2;
    int sc = tid & 3;

    float acc[2][8][4];
    #pragma unroll
    for (int i = 0; i < 2; i++)
        #pragma unroll
        for (int j = 0; j < 8; j++)
            #pragma unroll
            for (int q = 0; q < 4; q++) acc[i][j][q] = 0.0f;

    auto issue = [&](int c) {
        int seg = c >> 4, kofs = (c & 15) << 5;
        int asel = (seg == 1) ? 512 : 0;
        int bsel = (seg == 2) ? 512 : 0;
        const __nv_bfloat16* Ag = A + (size_t)m0 * 1024 + asel + kofs;
        const __nv_bfloat16* Bg = Bw + (size_t)n0 * 1024 + bsel + kofs;
        int buf = c & (NST - 1);
        uint32_t da = sbase + (uint32_t)buf * BUFB;
        uint32_t db = sbase + (uint32_t)(NST + buf) * BUFB;
        cpasync16(da + sr * ROWB + sc * 16,        Ag + (size_t)sr * 1024 + sc * 8);
        cpasync16(da + (sr + 64) * ROWB + sc * 16, Ag + (size_t)(sr + 64) * 1024 + sc * 8);
        cpasync16(db + sr * ROWB + sc * 16,        Bg + (size_t)sr * 1024 + sc * 8);
        cpasync16(db + (sr + 64) * ROWB + sc * 16, Bg + (size_t)(sr + 64) * 1024 + sc * 8);
        CP_COMMIT();
    };

    issue(0);
    issue(1);
    issue(2);

    int wm = wid & 3;
    int wn = wid >> 2;
    uint32_t a_row  = (uint32_t)(wm * 32 + (lane & 15));
    uint32_t a_colb = (uint32_t)((lane >> 4) * 16);
    uint32_t b_row  = (uint32_t)(wn * 64 + (lane & 7));
    uint32_t b_colb = (uint32_t)((lane >> 3) * 16);

    for (int c = 0; c < 48; c++) {
        if (c < 46)       asm volatile("cp.async.wait_group 2;" ::: "memory");
        else if (c == 46) asm volatile("cp.async.wait_group 1;" ::: "memory");
        else              asm volatile("cp.async.wait_group 0;" ::: "memory");
        __syncthreads();
        if (c + 3 < 48) issue(c + 3);

        int buf = c & (NST - 1);
        uint32_t sA = sbase + (uint32_t)buf * BUFB;
        uint32_t sB = sbase + (uint32_t)(NST + buf) * BUFB;

        uint32_t bf[8][4];
        #pragma unroll
        for (int nt = 0; nt < 8; nt++)
            ldsm4(bf[nt], sB + (b_row + nt * 8) * ROWB + b_colb);

        #pragma unroll
        for (int ks = 0; ks < 2; ks++) {
            uint32_t af[2][4];
            ldsm4(af[0], sA + a_row * ROWB + ks * 32 + a_colb);
            ldsm4(af[1], sA + (a_row + 16) * ROWB + ks * 32 + a_colb);
            #pragma unroll
            for (int mi = 0; mi < 2; mi++)
                #pragma unroll
                for (int nt = 0; nt < 8; nt++)
                    mma_bf16(acc[mi][nt], af[mi], bf[nt][2 * ks], bf[nt][2 * ks + 1]);
        }
    }

    int gid = lane >> 2, tig = lane & 3;
    float bv[16];
    #pragma unroll
    for (int nt = 0; nt < 8; nt++) {
        int col = n0 + wn * 64 + nt * 8 + 2 * tig;
        bv[nt * 2]     = bias[col];
        bv[nt * 2 + 1] = bias[col + 1];
    }
    #pragma unroll
    for (int mi = 0; mi < 2; mi++) {
        int mrow = m0 + wm * 32 + mi * 16 + gid;
        #pragma unroll
        for (int nt = 0; nt < 8; nt++) {
            int col = n0 + wn * 64 + nt * 8 + 2 * tig;
            float v0 = acc[mi][nt][0] + bv[nt * 2];
            float v1 = acc[mi][nt][1] + bv[nt * 2 + 1];
            float v2 = acc[mi][nt][2] + bv[nt * 2];
            float v3 = acc[mi][nt][3] + bv[nt * 2 + 1];
            if (mode == 0) {
                float* C = (float*)Cout;
                float2 p0 = {v0, v1}, p1 = {v2, v3};
                *(float2*)&C[(size_t)mrow * Ntot + col]       = p0;
                *(float2*)&C[(size_t)(mrow + 8) * Ntot + col] = p1;
            } else {
                __nv_bfloat16* C = (__nv_bfloat16*)Cout;
                v0 = tanhf(v0); v1 = tanhf(v1); v2 = tanhf(v2); v3 = tanhf(v3);
                __nv_bfloat16 h0 = __float2bfloat16(v0), h1 = __float2bfloat16(v1);
                __nv_bfloat16 h2 = __float2bfloat16(v2), h3 = __float2bfloat16(v3);
                __nv_bfloat16 l0 = __float2bfloat16(v0 - __bfloat162float(h0));
                __nv_bfloat16 l1 = __float2bfloat16(v1 - __bfloat162float(h1));
                __nv_bfloat16 l2 = __float2bfloat16(v2 - __bfloat162float(h2));
                __nv_bfloat16 l3 = __float2bfloat16(v3 - __bfloat162float(h3));
                __nv_bfloat162 ph0 = {h0, h1}, ph1 = {h2, h3};
                __nv_bfloat162 pl0 = {l0, l1}, pl1 = {l2, l3};
                *(__nv_bfloat162*)&C[(size_t)mrow * 1024 + col]             = ph0;
                *(__nv_bfloat162*)&C[(size_t)mrow * 1024 + 512 + col]       = pl0;
                *(__nv_bfloat162*)&C[(size_t)(mrow + 8) * 1024 + col]       = ph1;
                *(__nv_bfloat162*)&C[(size_t)(mrow + 8) * 1024 + 512 + col] = pl1;
            }
        }
    }
}

// ---------------------------------------------------------------------------
// Persistent GRU scan with mma.sync step GEMM.
//   gh[48x32] decomposed into 12 m16n8 tiles over ALL 8 warps:
//   warp w<4 -> tiles (m0, n_w) + (m2, n_w) (shared B fragment);
//   warp w>=4 -> tile (m1, n_{w-4}).  3 tiles (288 mma) per SMSP, balanced.
// ---------------------------------------------------------------------------
#define SC_STRIDE 520                            // bf16 elems/row -> 1040 B
#define SC_W_BYTES (96 * SC_STRIDE * 2)          // 99840
#define SC_H_BYTES (64 * SC_STRIDE * 2)          // 66560
#define SC_GH_F    (48 * 33)
#define SCAN_SMEM_BYTES (SC_W_BYTES + SC_H_BYTES + SC_GH_F * 4 + 256)

__global__ void __launch_bounds__(256, 1)
k_scan(const float* __restrict__ Whh, const float* __restrict__ bhh) {
    extern __shared__ char dynsm[];
    __nv_bfloat16* ws  = (__nv_bfloat16*)dynsm;
    __nv_bfloat16* hsb = (__nv_bfloat16*)(dynsm + SC_W_BYTES);
    float* gh  = (float*)(dynsm + SC_W_BYTES + SC_H_BYTES);
    float* bsh = gh + SC_GH_F;
    uint32_t ws_u = smem_u32(ws);
    uint32_t hs_u = smem_u32(hsb);

    int tid = threadIdx.x, wid = tid >> 5, lane = tid & 31;
    int blk = blockIdx.x;
    int bg = blk >> 5, dg = blk & 31;
    int d0 = dg << 4, b0 = bg << 5;

    // Load W slice once, split into bf16 hi/lo plane rows.
    for (int i = tid; i < 48 * 512; i += 256) {
        int j = i >> 9, k = i & 511;            // j = gate*16 + dc
        int g = j >> 4, dc = j & 15;
        float w = Whh[(size_t)(g * 512 + d0 + dc) * 512 + k];
        __nv_bfloat16 hi = __float2bfloat16(w);
        __nv_bfloat16 lo = __float2bfloat16(w - __bfloat162float(hi));
        ws[j * SC_STRIDE + k]        = hi;
        ws[(48 + j) * SC_STRIDE + k] = lo;
    }
    if (tid < 48) bsh[tid] = bhh[(tid >> 4) * 512 + d0 + (tid & 15)];
    __syncthreads();

    // tile mapping
    int na = wid & 3;                           // ntile (8 batches)
    int ma = (wid < 4) ? 0 : 1;                 // primary mtile
    bool two = (wid < 4);                       // warps 0-3 also do mtile 2
    uint32_t awA_hi = ws_u + (uint32_t)((ma * 16 + (lane & 15)) * 1040)
                    + ((lane >> 4) << 4);
    uint32_t awA_lo = awA_hi + 48u * 1040u;
    uint32_t awB_hi = ws_u + (uint32_t)((32 + (lane & 15)) * 1040)
                    + ((lane >> 4) << 4);       // mtile 2 rows 32..47
    uint32_t awB_lo = awB_hi + 48u * 1040u;
    uint32_t bh_hi = hs_u + (uint32_t)((na * 8 + (lane & 7)) * 1040)
                   + ((lane >> 3) << 4);
    uint32_t bh_lo = bh_hi + 32u * 1040u;

    int srow = tid >> 2;                        // staging row 0..63
    int scol = (tid & 3) << 7;                  // bf16 col base
    int splane = srow >> 5, sbatch = b0 + (srow & 31);
    uint32_t sdst = hs_u + (uint32_t)srow * 1040 + (uint32_t)scol * 2;

    int bi_a = tid >> 4;                        // epilogue: batches bi_a, +16
    int dc_a = tid & 15;
    int d_a = d0 + dc_a;
    int p = 0;

    for (int t = 0; t < HALF_T; t++) {
        // prefetch gx gate values (overlaps staging)
        size_t rowA = ((size_t)(b0 + bi_a) * 256 + t) * 1536;
        size_t rowB = ((size_t)(b0 + bi_a + 16) * 256 + t) * 1536;
        float gxrA = __ldcg(g_gx + rowA + d_a);
        float gxzA = __ldcg(g_gx + rowA + 512 + d_a);
        float gxnA = __ldcg(g_gx + rowA + 1024 + d_a);
        float gxrB = __ldcg(g_gx + rowB + d_a);
        float gxzB = __ldcg(g_gx + rowB + 512 + d_a);
        float gxnB = __ldcg(g_gx + rowB + 1024 + d_a);

        // stage h planes: tid<128 stages hi rows, tid>=128 stages lo rows
        {
            const __nv_bfloat16* src = g_h2 + ((size_t)p * BB + sbatch) * 1024
                                     + splane * 512 + scol;
            #pragma unroll
            for (int j = 0; j < 16; j++)
                cpasync16(sdst + j * 16, src + j * 8);
        }
        CP_COMMIT();
        if (tid < 128) asm volatile("cp.async.wait_group 0;" ::: "memory");
        __syncthreads();                         // hi plane visible

        // hi phase: (Whi + Wlo) x h_hi, lo copies still in flight
        float accA[4] = {0.f, 0.f, 0.f, 0.f};
        float accB[4] = {0.f, 0.f, 0.f, 0.f};
        #pragma unroll 4
        for (int k32 = 0; k32 < 16; k32++) {
            int kb = k32 << 6;
            uint32_t bh[4], a0[4], a1[4], l0[4], l1[4];
            ldsm4(bh, bh_hi + kb);
            ldsm4(a0, awA_hi + kb);
            ldsm4(a1, awA_hi + kb + 32);
            ldsm4(l0, awA_lo + kb);
            ldsm4(l1, awA_lo + kb + 32);
            mma_bf16(accA, a0, bh[0], bh[1]);
            mma_bf16(accA, a1, bh[2], bh[3]);
            mma_bf16(accA, l0, bh[0], bh[1]);
            mma_bf16(accA, l1, bh[2], bh[3]);
            if (two) {
                uint32_t c0[4], c1[4], e0[4], e1[4];
                ldsm4(c0, awB_hi + kb);
                ldsm4(c1, awB_hi + kb + 32);
                ldsm4(e0, awB_lo + kb);
                ldsm4(e1, awB_lo + kb + 32);
                mma_bf16(accB, c0, bh[0], bh[1]);
                mma_bf16(accB, c1, bh[2], bh[3]);
                mma_bf16(accB, e0, bh[0], bh[1]);
                mma_bf16(accB, e1, bh[2], bh[3]);
            }
        }
        if (tid >= 128) asm volatile("cp.async.wait_group 0;" ::: "memory");
        __syncthreads();                         // lo plane visible

        // lo phase: Whi x h_lo
        #pragma unroll 4
        for (int k32 = 0; k32 < 16; k32++) {
            int kb = k32 << 6;
            uint32_t bl[4], a0[4], a1[4];
            ldsm4(bl, bh_lo + kb);
            ldsm4(a0, awA_hi + kb);
            ldsm4(a1, awA_hi + kb + 32);
            mma_bf16(accA, a0, bl[0], bl[1]);
            mma_bf16(accA, a1, bl[2], bl[3]);
            if (two) {
                uint32_t c0[4], c1[4];
                ldsm4(c0, awB_hi + kb);
                ldsm4(c1, awB_hi + kb + 32);
                mma_bf16(accB, c0, bl[0], bl[1]);
                mma_bf16(accB, c1, bl[2], bl[3]);
            }
        }
        // write gh fragments
        {
            int r = lane >> 2, c2 = (lane & 3) << 1;
            int n = na * 8 + c2;
            int m = ma * 16 + r;
            gh[m * 33 + n]           = accA[0];
            gh[m * 33 + n + 1]       = accA[1];
            gh[(m + 8) * 33 + n]     = accA[2];
            gh[(m + 8) * 33 + n + 1] = accA[3];
            if (two) {
                int m2 = 32 + r;
                gh[m2 * 33 + n]           = accB[0];
                gh[m2 * 33 + n + 1]       = accB[1];
                gh[(m2 + 8) * 33 + n]     = accB[2];
                gh[(m2 + 8) * 33 + n + 1] = accB[3];
            }
        }
        __syncthreads();

        // epilogue: 2 outputs per thread
        #pragma unroll
        for (int half = 0; half < 2; half++) {
            int bi = bi_a + (half << 4);
            float gxr = half ? gxrB : gxrA;
            float gxz = half ? gxzB : gxzA;
            float gxn = half ? gxnB : gxnA;
            float ghr = gh[dc_a * 33 + bi]        + bsh[dc_a];
            float ghz = gh[(16 + dc_a) * 33 + bi] + bsh[16 + dc_a];
            float ghn = gh[(32 + dc_a) * 33 + bi] + bsh[32 + dc_a];
            float r = 1.0f / (1.0f + __expf(-(gxr + ghr)));
            float z = 1.0f / (1.0f + __expf(-(gxz + ghz)));
            float n = tanhf(gxn + r * ghn);
            float hold = __bfloat162float(hsb[bi * SC_STRIDE + d_a])
                       + __bfloat162float(hsb[(32 + bi) * SC_STRIDE + d_a]);
            float hn = (1.0f - z) * n + z * hold;
            int big = b0 + bi;
            __nv_bfloat16 hi = __float2bfloat16(hn);
            __nv_bfloat16 lo = __float2bfloat16(hn - __bfloat162float(hi));
            if (t < HALF_T - 1) {
                size_t hrow = ((size_t)(p ^ 1) * BB + big) * 1024;
                g_h2[hrow + d_a]       = hi;
                g_h2[hrow + 512 + d_a] = lo;
            }
            size_t erow = ((size_t)big * 256 + t) * 1024;
            g_e2[erow + d_a]       = hi;
            g_e2[erow + 512 + d_a] = lo;
        }

        // per-batch-group grid barrier (skipped on the final step)
        if (t < HALF_T - 1) {
            __threadfence();
            __syncthreads();
            if (tid == 0) {
                unsigned target = (unsigned)(t + 1) * 32u;
                atomicAdd(&g_ctr4[bg * 32], 1u);
                volatile unsigned* vc = &g_ctr4[bg * 32];
                while (*vc < target) { __nanosleep(32); }
            }
            __syncthreads();
        }
        p ^= 1;
    }
}

// ---------------------------------------------------------------------------
// Fused head: out[m] = logsoftmax(f[m]) @ W_comb^T + b_comb
// ---------------------------------------------------------------------------
__global__ void __launch_bounds__(256)
k_final(const float* __restrict__ X, float* __restrict__ out) {
    __shared__ float Wc[NCLS * DD];
    __shared__ float ss[NCLS], bc[NCLS];
    int tid = threadIdx.x;
    for (int idx = tid; idx < NCLS * DD; idx += 256) Wc[idx] = g_Wc[idx];
    if (tid < NCLS) { ss[tid] = g_s[tid]; bc[tid] = g_bc[tid]; }
    __syncthreads();

    int w = tid >> 5, l = tid & 31;
    int m = (blockIdx.x << 3) + w;
    const float* xr = X + (size_t)m * DD;

    float f[16];
    #pragma unroll
    for (int i = 0; i < 16; i++) f[i] = xr[i * 32 + l];

    float mx = f[0];
    #pragma unroll
    for (int i = 1; i < 16; i++) mx = fmaxf(mx, f[i]);
    #pragma unroll
    for (int off = 16; off > 0; off >>= 1)
        mx = fmaxf(mx, __shfl_xor_sync(0xffffffffu, mx, off));

    float se = 0.0f;
    #pragma unroll
    for (int i = 0; i < 16; i++) se += __expf(f[i] - mx);
    #pragma unroll
    for (int off = 16; off > 0; off >>= 1)
        se += __shfl_xor_sync(0xffffffffu, se, off);
    float c = mx + __logf(se);

    #pragma unroll
    for (int n = 0; n < NCLS; n++) {
        float dot = 0.0f;
        const float* wr = Wc + n * DD;
        #pragma unroll
        for (int i = 0; i < 16; i++) dot += f[i] * wr[i * 32 + l];
        #pragma unroll
        for (int off = 16; off > 0; off >>= 1)
            dot += __shfl_xor_sync(0xffffffffu, dot, off);
        if (l == 0) out[m * NCLS + n] = dot - c * ss[n] + bc[n];
    }
}

// ---------------------------------------------------------------------------
// kernel_launch — ordered so k_scan is launch index 5 (ncu -s 5 -c 1 target)
// ---------------------------------------------------------------------------
extern "C" void kernel_launch(void* const* d_in, const int* in_sizes, int n_in,
                              void* d_out, int out_size) {
    (void)in_sizes; (void)out_size;
    if (n_in < 17) return;
    const float* x0     = (const float*)d_in[0];
    const float* W_ih   = (const float*)d_in[3];
    const float* W_hh   = (const float*)d_in[4];
    const float* b_ih   = (const float*)d_in[5];
    const float* b_hh   = (const float*)d_in[6];
    const float* W1     = (const float*)d_in[7];
    const float* bb1    = (const float*)d_in[8];
    const float* W2     = (const float*)d_in[9];
    const float* bb2    = (const float*)d_in[10];
    const float* W3     = (const float*)d_in[11];
    const float* bb3    = (const float*)d_in[12];
    const float* W_half = (const float*)d_in[13];
    const float* b_half = (const float*)d_in[14];
    const float* W_out  = (const float*)d_in[15];
    const float* b_out  = (const float*)d_in[16];
    float* out = (float*)d_out;

    float *gx, *x3;
    __nv_bfloat16 *A0, *e2, *x1b, *x2b, *Wih2, *W12, *W22, *W32;
    cudaGetSymbolAddress((void**)&gx,   g_gx);
    cudaGetSymbolAddress((void**)&x3,   g_x3);
    cudaGetSymbolAddress((void**)&A0,   g_A0);
    cudaGetSymbolAddress((void**)&e2,   g_e2);
    cudaGetSymbolAddress((void**)&x1b,  g_x1b);
    cudaGetSymbolAddress((void**)&x2b,  g_x2b);
    cudaGetSymbolAddress((void**)&Wih2, g_Wih2);
    cudaGetSymbolAddress((void**)&W12,  g_W12);
    cudaGetSymbolAddress((void**)&W22,  g_W22);
    cudaGetSymbolAddress((void**)&W32,  g_W32);

    cudaFuncSetAttribute(k_scan, cudaFuncAttributeMaxDynamicSharedMemorySize,
                         SCAN_SMEM_BYTES);
    cudaFuncSetAttribute(k_mma_gemm, cudaFuncAttributeMaxDynamicSharedMemorySize,
                         GEMM_SMEM);

    // 0,1: input/weight splits needed by gx GEMM
    k_split<<<(MROWS * 128) / 256, 256>>>(x0, A0, MROWS, 1);
    k_split<<<(1536 * 128) / 256, 256>>>(W_ih, Wih2, 1536, 0);
    // 2: init h planes + barrier counters
    k_init<<<256, 256>>>();
    // 3: gx = x0 @ W_ih^T + b_ih   [32768 x 1536]
    k_mma_gemm<<<256 * 12, 256, GEMM_SMEM>>>(A0, Wih2, b_ih, gx, 1536, 12, 0);
    // 4: head fold (independent)
    k_prep1<<<14, 256>>>(W_half, W_out);
    // 5: GRU scan (PROFILED)
    k_scan<<<128, 256, SCAN_SMEM_BYTES>>>(W_hh, b_hh);
    // 6: head fold part 2
    k_prep2<<<1, 256>>>(W_out, b_half, b_out);
    // 7-9: FFN weight splits
    k_split<<<(512 * 128) / 256, 256>>>(W1, W12, 512, 0);
    k_split<<<(512 * 128) / 256, 256>>>(W2, W22, 512, 0);
    k_split<<<(512 * 128) / 256, 256>>>(W3, W32, 512, 0);
    // 10-12: FFN
    k_mma_gemm<<<256 * 4, 256, GEMM_SMEM>>>(e2,  W12, bb1, x1b, 512, 4, 1);
    k_mma_gemm<<<256 * 4, 256, GEMM_SMEM>>>(x1b, W22, bb2, x2b, 512, 4, 1);
    k_mma_gemm<<<256 * 4, 256, GEMM_SMEM>>>(x2b, W32, bb3, x3,  512, 4, 0);
    // 13: fused log_softmax + combined classifier head
    k_final<<<MROWS / 8, 256>>>(x3, out);
}

// round 10
// speedup vs baseline: 1.4054x; 1.4054x over previous
#include <cuda_runtime.h>
#include <cuda_bf16.h>
#include <cstddef>
#include <cstdint>

// Problem constants
#define BB     128
#define TT     512
#define HALF_T 256
#define DD     512
#define NCLS   7
#define MROWS  (BB * HALF_T)   // 32768 rows fed to FFN / head

typedef unsigned long long ull;

// ---------------------------------------------------------------------------
// mma.sync / ldmatrix / cp.async / bulk-DMA helpers (baseline PTX, sm_100-safe)
// ---------------------------------------------------------------------------
__device__ __forceinline__ uint32_t smem_u32(const void* p) {
    uint32_t a;
    asm("{ .reg .u64 t; cvta.to.shared.u64 t, %1; cvt.u32.u64 %0, t; }"
        : "=r"(a) : "l"(p));
    return a;
}
__device__ __forceinline__ void ldsm4(uint32_t* r, uint32_t addr) {
    asm volatile("ldmatrix.sync.aligned.m8n8.x4.shared.b16 {%0,%1,%2,%3}, [%4];"
        : "=r"(r[0]), "=r"(r[1]), "=r"(r[2]), "=r"(r[3]) : "r"(addr));
}
__device__ __forceinline__ void mma_bf16(float* d, const uint32_t* a,
                                         uint32_t b0, uint32_t b1) {
    asm volatile("mma.sync.aligned.m16n8k16.row.col.f32.bf16.bf16.f32 "
        "{%0,%1,%2,%3}, {%4,%5,%6,%7}, {%8,%9}, {%0,%1,%2,%3};"
        : "+f"(d[0]), "+f"(d[1]), "+f"(d[2]), "+f"(d[3])
        : "r"(a[0]), "r"(a[1]), "r"(a[2]), "r"(a[3]), "r"(b0), "r"(b1));
}
__device__ __forceinline__ void cpasync16(uint32_t dst, const void* src) {
    asm volatile("cp.async.cg.shared.global [%0], [%1], 16;"
                 :: "r"(dst), "l"(src));
}
#define CP_COMMIT() asm volatile("cp.async.commit_group;" ::: "memory")

// bulk DMA: gmem -> smem, completion via mbarrier complete_tx
__device__ __forceinline__ void bulkcp(uint32_t dst, const void* src,
                                       uint32_t bytes, uint32_t mbar) {
    asm volatile(
        "cp.async.bulk.shared::cluster.global.mbarrier::complete_tx::bytes "
        "[%0], [%1], %2, [%3];"
        :: "r"(dst), "l"(src), "r"(bytes), "r"(mbar) : "memory");
}
__device__ __forceinline__ void mbar_init(uint32_t mbar, uint32_t cnt) {
    asm volatile("mbarrier.init.shared.b64 [%0], %1;"
                 :: "r"(mbar), "r"(cnt) : "memory");
}
__device__ __forceinline__ void mbar_expect(uint32_t mbar, uint32_t bytes) {
    asm volatile("mbarrier.arrive.expect_tx.shared.b64 _, [%0], %1;"
                 :: "r"(mbar), "r"(bytes) : "memory");
}
__device__ __forceinline__ void mbar_wait(uint32_t mbar, uint32_t parity) {
    asm volatile("{\n\t.reg .pred P;\n\tWL%=:\n\t"
                 "mbarrier.try_wait.parity.acquire.cta.shared::cta.b64 P, [%0], %1;\n\t"
                 "@!P bra WL%=;\n\t}" :: "r"(mbar), "r"(parity) : "memory");
}

// ---------------------------------------------------------------------------
// Device scratch
// ---------------------------------------------------------------------------
__device__ float g_gx[MROWS * 1536];             // input projections (fp32)
__device__ float g_x3[MROWS * DD];               // FFN layer-3 output (fp32)
__device__ __nv_bfloat16 g_A0 [MROWS * 1024];    // x0 split planes (hi|lo)
__device__ __nv_bfloat16 g_e2 [MROWS * 1024];    // emotions split planes
__device__ __nv_bfloat16 g_x1b[MROWS * 1024];
__device__ __nv_bfloat16 g_x2b[MROWS * 1024];
__device__ __nv_bfloat16 g_Wih2[1536 * 1024];    // weight split planes
__device__ __nv_bfloat16 g_W12 [512 * 1024];
__device__ __nv_bfloat16 g_W22 [512 * 1024];
__device__ __nv_bfloat16 g_W32 [512 * 1024];
// GRU h planes, padded layout for bulk DMA:
// [2 bufs][4 groups][2 planes][32 batches][520]  (row = plane*32+batch)
#define HROW 520
#define HGRP (2 * 32 * HROW)                     // 33280 elems / 66560 B
__device__ __nv_bfloat16 g_h2[2 * 4 * HGRP];
__device__ float g_Wc[NCLS * DD];
__device__ float g_s [NCLS];
__device__ float g_bc[NCLS];
__device__ unsigned g_ctr4[4 * 32];              // barrier counters, 128B apart

// ---------------------------------------------------------------------------
// Init: zero h planes buffer 0 + barrier counters (reset every graph replay)
// ---------------------------------------------------------------------------
__global__ void k_init() {
    int idx = blockIdx.x * 256 + threadIdx.x;   // 520 blocks = 133120 threads
    if (idx < 4 * HGRP / 2) {
        ((__nv_bfloat162*)g_h2)[idx] = __nv_bfloat162{__nv_bfloat16(0.f),
                                                      __nv_bfloat16(0.f)};
    }
    if (idx < 4) g_ctr4[idx * 32] = 0u;
}

// ---------------------------------------------------------------------------
// prep1/prep2: fold log_softmax + classifier head
// ---------------------------------------------------------------------------
__global__ void k_prep1(const float* __restrict__ W_half,
                        const float* __restrict__ W_out) {
    int idx = blockIdx.x * 256 + threadIdx.x;
    if (idx >= NCLS * DD) return;
    int n = idx / DD, k = idx % DD;
    float s = 0.0f;
    for (int j = 0; j < 256; j++)
        s += W_out[n * 256 + j] * W_half[j * DD + k];
    g_Wc[idx] = s;
}
__global__ void k_prep2(const float* __restrict__ W_out,
                        const float* __restrict__ b_half,
                        const float* __restrict__ b_out) {
    int tid = threadIdx.x;
    int w = tid >> 5, l = tid & 31;
    if (w < NCLS) {
        float s = 0.0f;
        #pragma unroll
        for (int i = 0; i < 16; i++) s += g_Wc[w * DD + i * 32 + l];
        #pragma unroll
        for (int off = 16; off > 0; off >>= 1)
            s += __shfl_xor_sync(0xffffffffu, s, off);
        if (l == 0) g_s[w] = s;
    }
    if (tid < NCLS) {
        float b = b_out[tid];
        for (int j = 0; j < 256; j++)
            b += W_out[tid * 256 + j] * b_half[j];
        g_bc[tid] = b;
    }
}

// ---------------------------------------------------------------------------
// k_split: fp32 [rows,512] -> bf16 hi/lo planes [rows,1024]
// ---------------------------------------------------------------------------
__global__ void k_split(const float* __restrict__ src,
                        __nv_bfloat16* __restrict__ dst,
                        int nrows, int perm) {
    int idx = blockIdx.x * 256 + threadIdx.x;
    if (idx >= nrows * 128) return;
    int r = idx >> 7, c4 = (idx & 127) << 2;
    size_t so = perm ? ((size_t)((r >> 8) * 512 + (r & 255)) * 512)
                     : ((size_t)r * 512);
    float4 v = *(const float4*)(src + so + c4);
    __nv_bfloat16 h[4], lo[4];
    float vv[4] = {v.x, v.y, v.z, v.w};
    #pragma unroll
    for (int i = 0; i < 4; i++) {
        h[i] = __float2bfloat16(vv[i]);
        lo[i] = __float2bfloat16(vv[i] - __bfloat162float(h[i]));
    }
    *(ull*)(dst + (size_t)r * 1024 + c4)       = *(ull*)h;
    *(ull*)(dst + (size_t)r * 1024 + 512 + c4) = *(ull*)lo;
}

// ---------------------------------------------------------------------------
// mma.sync bf16-split GEMM, 3-stage cp.async pipeline (proven R7 config).
//   C[m,n] = act( sum_k A[m,k]*B[n,k] + bias[n] ),  K' = 1536 (3 segments).
// ---------------------------------------------------------------------------
#define ROWB 80          // padded smem row: 32 bf16 (64B) + 16B pad
#define BUFB (128 * ROWB)
#define NST  3
#define GEMM_SMEM (2 * NST * BUFB)   // 61440

__global__ void __launch_bounds__(256, 2)
k_mma_gemm(const __nv_bfloat16* __restrict__ A,
           const __nv_bfloat16* __restrict__ Bw,
           const float* __restrict__ bias,
           void* __restrict__ Cout,
           int Ntot, int n_tiles, int mode) {
    extern __shared__ __align__(16) char smc[];
    uint32_t sbase = smem_u32(smc);
    int tid = threadIdx.x, wid = tid >> 5, lane = tid & 31;
    int m0 = (blockIdx.x / n_tiles) << 7;
    int n0 = (blockIdx.x % n_tiles) << 7;

    int sr = tid >> 2;
    int sc = tid & 3;

    float acc[2][8][4];
    #pragma unroll
    for (int i = 0; i < 2; i++)
        #pragma unroll
        for (int j = 0; j < 8; j++)
            #pragma unroll
            for (int q = 0; q < 4; q++) acc[i][j][q] = 0.0f;

    auto issue = [&](int c) {
        int seg = c >> 4, kofs = (c & 15) << 5;
        int asel = (seg == 1) ? 512 : 0;
        int bsel = (seg == 2) ? 512 : 0;
        const __nv_bfloat16* Ag = A + (size_t)m0 * 1024 + asel + kofs;
        const __nv_bfloat16* Bg = Bw + (size_t)n0 * 1024 + bsel + kofs;
        int buf = c % NST;
        uint32_t da = sbase + (uint32_t)buf * BUFB;
        uint32_t db = sbase + (uint32_t)(NST + buf) * BUFB;
        cpasync16(da + sr * ROWB + sc * 16,        Ag + (size_t)sr * 1024 + sc * 8);
        cpasync16(da + (sr + 64) * ROWB + sc * 16, Ag + (size_t)(sr + 64) * 1024 + sc * 8);
        cpasync16(db + sr * ROWB + sc * 16,        Bg + (size_t)sr * 1024 + sc * 8);
        cpasync16(db + (sr + 64) * ROWB + sc * 16, Bg + (size_t)(sr + 64) * 1024 + sc * 8);
        CP_COMMIT();
    };

    issue(0);
    issue(1);

    int wm = wid & 3;
    int wn = wid >> 2;
    uint32_t a_row  = (uint32_t)(wm * 32 + (lane & 15));
    uint32_t a_colb = (uint32_t)((lane >> 4) * 16);
    uint32_t b_row  = (uint32_t)(wn * 64 + (lane & 7));
    uint32_t b_colb = (uint32_t)((lane >> 3) * 16);

    for (int c = 0; c < 48; c++) {
        if (c < 47) asm volatile("cp.async.wait_group 1;" ::: "memory");
        else        asm volatile("cp.async.wait_group 0;" ::: "memory");
        __syncthreads();
        if (c + 2 < 48) issue(c + 2);

        int buf = c % NST;
        uint32_t sA = sbase + (uint32_t)buf * BUFB;
        uint32_t sB = sbase + (uint32_t)(NST + buf) * BUFB;

        uint32_t bf[8][4];
        #pragma unroll
        for (int nt = 0; nt < 8; nt++)
            ldsm4(bf[nt], sB + (b_row + nt * 8) * ROWB + b_colb);

        #pragma unroll
        for (int ks = 0; ks < 2; ks++) {
            uint32_t af[2][4];
            ldsm4(af[0], sA + a_row * ROWB + ks * 32 + a_colb);
            ldsm4(af[1], sA + (a_row + 16) * ROWB + ks * 32 + a_colb);
            #pragma unroll
            for (int mi = 0; mi < 2; mi++)
                #pragma unroll
                for (int nt = 0; nt < 8; nt++)
                    mma_bf16(acc[mi][nt], af[mi], bf[nt][2 * ks], bf[nt][2 * ks + 1]);
        }
    }

    int gid = lane >> 2, tig = lane & 3;
    float bv[16];
    #pragma unroll
    for (int nt = 0; nt < 8; nt++) {
        int col = n0 + wn * 64 + nt * 8 + 2 * tig;
        bv[nt * 2]     = bias[col];
        bv[nt * 2 + 1] = bias[col + 1];
    }
    #pragma unroll
    for (int mi = 0; mi < 2; mi++) {
        int mrow = m0 + wm * 32 + mi * 16 + gid;
        #pragma unroll
        for (int nt = 0; nt < 8; nt++) {
            int col = n0 + wn * 64 + nt * 8 + 2 * tig;
            float v0 = acc[mi][nt][0] + bv[nt * 2];
            float v1 = acc[mi][nt][1] + bv[nt * 2 + 1];
            float v2 = acc[mi][nt][2] + bv[nt * 2];
            float v3 = acc[mi][nt][3] + bv[nt * 2 + 1];
            if (mode == 0) {
                float* C = (float*)Cout;
                float2 p0 = {v0, v1}, p1 = {v2, v3};
                *(float2*)&C[(size_t)mrow * Ntot + col]       = p0;
                *(float2*)&C[(size_t)(mrow + 8) * Ntot + col] = p1;
            } else {
                __nv_bfloat16* C = (__nv_bfloat16*)Cout;
                v0 = tanhf(v0); v1 = tanhf(v1); v2 = tanhf(v2); v3 = tanhf(v3);
                __nv_bfloat16 h0 = __float2bfloat16(v0), h1 = __float2bfloat16(v1);
                __nv_bfloat16 h2 = __float2bfloat16(v2), h3 = __float2bfloat16(v3);
                __nv_bfloat16 l0 = __float2bfloat16(v0 - __bfloat162float(h0));
                __nv_bfloat16 l1 = __float2bfloat16(v1 - __bfloat162float(h1));
                __nv_bfloat16 l2 = __float2bfloat16(v2 - __bfloat162float(h2));
                __nv_bfloat16 l3 = __float2bfloat16(v3 - __bfloat162float(h3));
                __nv_bfloat162 ph0 = {h0, h1}, ph1 = {h2, h3};
                __nv_bfloat162 pl0 = {l0, l1}, pl1 = {l2, l3};
                *(__nv_bfloat162*)&C[(size_t)mrow * 1024 + col]             = ph0;
                *(__nv_bfloat162*)&C[(size_t)mrow * 1024 + 512 + col]       = pl0;
                *(__nv_bfloat162*)&C[(size_t)(mrow + 8) * 1024 + col]       = ph1;
                *(__nv_bfloat162*)&C[(size_t)(mrow + 8) * 1024 + 512 + col] = pl1;
            }
        }
    }
}

// ---------------------------------------------------------------------------
// Persistent GRU scan (R7 6-warp mma) with bulk-DMA h staging.
//   Per step: ONE thread issues 2 cp.async.bulk copies (hi/lo plane blocks,
//   33280 B each) into the padded smem tile; mbarrier completion.
//   hi-phase mma overlaps the lo-plane DMA.
// ---------------------------------------------------------------------------
#define SC_STRIDE 520                            // bf16 elems/row -> 1040 B
#define SC_W_BYTES (96 * SC_STRIDE * 2)          // 99840
#define SC_H_BYTES (64 * SC_STRIDE * 2)          // 66560
#define SC_GH_F    (48 * 33)
#define SCAN_SMEM_BYTES (SC_W_BYTES + SC_H_BYTES + SC_GH_F * 4 + 256)

__global__ void __launch_bounds__(256, 1)
k_scan(const float* __restrict__ Whh, const float* __restrict__ bhh) {
    extern __shared__ __align__(16) char dynsm[];
    __nv_bfloat16* ws  = (__nv_bfloat16*)dynsm;
    __nv_bfloat16* hsb = (__nv_bfloat16*)(dynsm + SC_W_BYTES);
    float* gh  = (float*)(dynsm + SC_W_BYTES + SC_H_BYTES);
    float* bsh = gh + SC_GH_F;
    uint32_t ws_u = smem_u32(ws);
    uint32_t hs_u = smem_u32(hsb);
    uint32_t mbA = smem_u32(dynsm + SC_W_BYTES + SC_H_BYTES + SC_GH_F * 4 + 192);
    uint32_t mbB = mbA + 8;

    int tid = threadIdx.x, wid = tid >> 5, lane = tid & 31;
    int blk = blockIdx.x;
    int bg = blk >> 5, dg = blk & 31;
    int d0 = dg << 4, b0 = bg << 5;
    (void)b0;

    // Load W slice once, split into bf16 hi/lo plane rows.
    for (int i = tid; i < 48 * 512; i += 256) {
        int j = i >> 9, k = i & 511;            // j = gate*16 + dc
        int g = j >> 4, dc = j & 15;
        float w = Whh[(size_t)(g * 512 + d0 + dc) * 512 + k];
        __nv_bfloat16 hi = __float2bfloat16(w);
        __nv_bfloat16 lo = __float2bfloat16(w - __bfloat162float(hi));
        ws[j * SC_STRIDE + k]        = hi;
        ws[(48 + j) * SC_STRIDE + k] = lo;
    }
    if (tid < 48) bsh[tid] = bhh[(tid >> 4) * 512 + d0 + (tid & 15)];
    if (tid == 0) { mbar_init(mbA, 1); mbar_init(mbB, 1); }
    __syncthreads();

    int mt = wid % 3, nh = wid / 3;             // mma mapping (wid < 6)
    // mma fragment addresses (constant per thread)
    uint32_t aw_hi = ws_u + (uint32_t)((mt * 16 + (lane & 15)) * 1040)
                   + ((lane >> 4) << 4);
    uint32_t aw_lo = aw_hi + 48u * 1040u;
    uint32_t bh_hi = hs_u + (uint32_t)((nh * 16 + (lane & 7)) * 1040)
                   + ((lane >> 3) << 4);
    uint32_t bh_lo = bh_hi + 32u * 1040u;

    int bi_a = tid >> 4;                        // epilogue: batches bi_a, +16
    int dc_a = tid & 15;
    int d_a = d0 + dc_a;
    int p = 0;

    for (int t = 0; t < HALF_T; t++) {
        // prefetch gx gate values (overlaps DMA)
        size_t rowA = ((size_t)(b0 + bi_a) * 256 + t) * 1536;
        size_t rowB = ((size_t)(b0 + bi_a + 16) * 256 + t) * 1536;
        float gxrA = __ldcg(g_gx + rowA + d_a);
        float gxzA = __ldcg(g_gx + rowA + 512 + d_a);
        float gxnA = __ldcg(g_gx + rowA + 1024 + d_a);
        float gxrB = __ldcg(g_gx + rowB + d_a);
        float gxzB = __ldcg(g_gx + rowB + 512 + d_a);
        float gxnB = __ldcg(g_gx + rowB + 1024 + d_a);

        // bulk-DMA stage h planes (hi block then lo block)
        if (tid == 0) {
            const __nv_bfloat16* src = g_h2 + ((size_t)p * 4 + bg) * HGRP;
            mbar_expect(mbA, 33280u);
            mbar_expect(mbB, 33280u);
            bulkcp(hs_u,          src,         33280u, mbA);
            bulkcp(hs_u + 33280u, src + 16640, 33280u, mbB);
        }
        mbar_wait(mbA, (uint32_t)(t & 1));      // hi plane visible

        // hi phase: (Whi + Wlo) x h_hi, lo DMA still in flight
        float acc[2][4];
        if (wid < 6) {
            #pragma unroll
            for (int nt = 0; nt < 2; nt++)
                #pragma unroll
                for (int q = 0; q < 4; q++) acc[nt][q] = 0.0f;
            #pragma unroll 4
            for (int k32 = 0; k32 < 16; k32++) {
                int kb = k32 << 6;
                uint32_t ah0[4], ah1[4], al0[4], al1[4], bf0[4], bf1[4];
                ldsm4(ah0, aw_hi + kb);
                ldsm4(ah1, aw_hi + kb + 32);
                ldsm4(al0, aw_lo + kb);
                ldsm4(al1, aw_lo + kb + 32);
                ldsm4(bf0, bh_hi + kb);
                ldsm4(bf1, bh_hi + kb + 8 * 1040);
                mma_bf16(acc[0], ah0, bf0[0], bf0[1]);
                mma_bf16(acc[1], ah0, bf1[0], bf1[1]);
                mma_bf16(acc[0], ah1, bf0[2], bf0[3]);
                mma_bf16(acc[1], ah1, bf1[2], bf1[3]);
                mma_bf16(acc[0], al0, bf0[0], bf0[1]);
                mma_bf16(acc[1], al0, bf1[0], bf1[1]);
                mma_bf16(acc[0], al1, bf0[2], bf0[3]);
                mma_bf16(acc[1], al1, bf1[2], bf1[3]);
            }
        }
        mbar_wait(mbB, (uint32_t)(t & 1));      // lo plane visible

        if (wid < 6) {
            #pragma unroll 4
            for (int k32 = 0; k32 < 16; k32++) {
                int kb = k32 << 6;
                uint32_t bl0[4], bl1[4], ah0[4], ah1[4];
                ldsm4(bl0, bh_lo + kb);
                ldsm4(bl1, bh_lo + kb + 8 * 1040);
                ldsm4(ah0, aw_hi + kb);
                ldsm4(ah1, aw_hi + kb + 32);
                mma_bf16(acc[0], ah0, bl0[0], bl0[1]);
                mma_bf16(acc[1], ah0, bl1[0], bl1[1]);
                mma_bf16(acc[0], ah1, bl0[2], bl0[3]);
                mma_bf16(acc[1], ah1, bl1[2], bl1[3]);
            }
            // write gh fragments
            int r = lane >> 2, c = (lane & 3) << 1;
            #pragma unroll
            for (int nt = 0; nt < 2; nt++) {
                int n = nh * 16 + nt * 8 + c;
                int m = mt * 16 + r;
                gh[m * 33 + n]           = acc[nt][0];
                gh[m * 33 + n + 1]       = acc[nt][1];
                gh[(m + 8) * 33 + n]     = acc[nt][2];
                gh[(m + 8) * 33 + n + 1] = acc[nt][3];
            }
        }
        __syncthreads();

        // epilogue: 2 outputs per thread
        #pragma unroll
        for (int half = 0; half < 2; half++) {
            int bi = bi_a + (half << 4);
            float gxr = half ? gxrB : gxrA;
            float gxz = half ? gxzB : gxzA;
            float gxn = half ? gxnB : gxnA;
            float ghr = gh[dc_a * 33 + bi]        + bsh[dc_a];
            float ghz = gh[(16 + dc_a) * 33 + bi] + bsh[16 + dc_a];
            float ghn = gh[(32 + dc_a) * 33 + bi] + bsh[32 + dc_a];
            float r = 1.0f / (1.0f + __expf(-(gxr + ghr)));
            float z = 1.0f / (1.0f + __expf(-(gxz + ghz)));
            float n = tanhf(gxn + r * ghn);
            float hold = __bfloat162float(hsb[bi * SC_STRIDE + d_a])
                       + __bfloat162float(hsb[(32 + bi) * SC_STRIDE + d_a]);
            float hn = (1.0f - z) * n + z * hold;
            int big = b0 + bi;
            __nv_bfloat16 hi = __float2bfloat16(hn);
            __nv_bfloat16 lo = __float2bfloat16(hn - __bfloat162float(hi));
            if (t < HALF_T - 1) {
                size_t gb = ((size_t)(p ^ 1) * 4 + bg) * HGRP;
                g_h2[gb + bi * HROW + d_a]         = hi;
                g_h2[gb + 16640 + bi * HROW + d_a] = lo;
            }
            size_t erow = ((size_t)big * 256 + t) * 1024;
            g_e2[erow + d_a]       = hi;
            g_e2[erow + 512 + d_a] = lo;
        }

        // per-batch-group grid barrier (skipped on the final step)
        if (t < HALF_T - 1) {
            __threadfence();
            __syncthreads();
            if (tid == 0) {
                unsigned target = (unsigned)(t + 1) * 32u;
                atomicAdd(&g_ctr4[bg * 32], 1u);
                volatile unsigned* vc = &g_ctr4[bg * 32];
                while (*vc < target) { }
            }
            __syncthreads();
        }
        p ^= 1;
    }
}

// ---------------------------------------------------------------------------
// Fused head: out[m] = logsoftmax(f[m]) @ W_comb^T + b_comb
// ---------------------------------------------------------------------------
__global__ void __launch_bounds__(256)
k_final(const float* __restrict__ X, float* __restrict__ out) {
    __shared__ float Wc[NCLS * DD];
    __shared__ float ss[NCLS], bc[NCLS];
    int tid = threadIdx.x;
    for (int idx = tid; idx < NCLS * DD; idx += 256) Wc[idx] = g_Wc[idx];
    if (tid < NCLS) { ss[tid] = g_s[tid]; bc[tid] = g_bc[tid]; }
    __syncthreads();

    int w = tid >> 5, l = tid & 31;
    int m = (blockIdx.x << 3) + w;
    const float* xr = X + (size_t)m * DD;

    float f[16];
    #pragma unroll
    for (int i = 0; i < 16; i++) f[i] = xr[i * 32 + l];

    float mx = f[0];
    #pragma unroll
    for (int i = 1; i < 16; i++) mx = fmaxf(mx, f[i]);
    #pragma unroll
    for (int off = 16; off > 0; off >>= 1)
        mx = fmaxf(mx, __shfl_xor_sync(0xffffffffu, mx, off));

    float se = 0.0f;
    #pragma unroll
    for (int i = 0; i < 16; i++) se += __expf(f[i] - mx);
    #pragma unroll
    for (int off = 16; off > 0; off >>= 1)
        se += __shfl_xor_sync(0xffffffffu, se, off);
    float c = mx + __logf(se);

    #pragma unroll
    for (int n = 0; n < NCLS; n++) {
        float dot = 0.0f;
        const float* wr = Wc + n * DD;
        #pragma unroll
        for (int i = 0; i < 16; i++) dot += f[i] * wr[i * 32 + l];
        #pragma unroll
        for (int off = 16; off > 0; off >>= 1)
            dot += __shfl_xor_sync(0xffffffffu, dot, off);
        if (l == 0) out[m * NCLS + n] = dot - c * ss[n] + bc[n];
    }
}

// ---------------------------------------------------------------------------
// kernel_launch — ordered so k_scan is launch index 5 (ncu -s 5 -c 1 target)
// ---------------------------------------------------------------------------
extern "C" void kernel_launch(void* const* d_in, const int* in_sizes, int n_in,
                              void* d_out, int out_size) {
    (void)in_sizes; (void)out_size;
    if (n_in < 17) return;
    const float* x0     = (const float*)d_in[0];
    const float* W_ih   = (const float*)d_in[3];
    const float* W_hh   = (const float*)d_in[4];
    const float* b_ih   = (const float*)d_in[5];
    const float* b_hh   = (const float*)d_in[6];
    const float* W1     = (const float*)d_in[7];
    const float* bb1    = (const float*)d_in[8];
    const float* W2     = (const float*)d_in[9];
    const float* bb2    = (const float*)d_in[10];
    const float* W3     = (const float*)d_in[11];
    const float* bb3    = (const float*)d_in[12];
    const float* W_half = (const float*)d_in[13];
    const float* b_half = (const float*)d_in[14];
    const float* W_out  = (const float*)d_in[15];
    const float* b_out  = (const float*)d_in[16];
    float* out = (float*)d_out;

    float *gx, *x3;
    __nv_bfloat16 *A0, *e2, *x1b, *x2b, *Wih2, *W12, *W22, *W32;
    cudaGetSymbolAddress((void**)&gx,   g_gx);
    cudaGetSymbolAddress((void**)&x3,   g_x3);
    cudaGetSymbolAddress((void**)&A0,   g_A0);
    cudaGetSymbolAddress((void**)&e2,   g_e2);
    cudaGetSymbolAddress((void**)&x1b,  g_x1b);
    cudaGetSymbolAddress((void**)&x2b,  g_x2b);
    cudaGetSymbolAddress((void**)&Wih2, g_Wih2);
    cudaGetSymbolAddress((void**)&W12,  g_W12);
    cudaGetSymbolAddress((void**)&W22,  g_W22);
    cudaGetSymbolAddress((void**)&W32,  g_W32);

    cudaFuncSetAttribute(k_scan, cudaFuncAttributeMaxDynamicSharedMemorySize,
                         SCAN_SMEM_BYTES);
    cudaFuncSetAttribute(k_mma_gemm, cudaFuncAttributeMaxDynamicSharedMemorySize,
                         GEMM_SMEM);

    // 0,1: input/weight splits needed by gx GEMM
    k_split<<<(MROWS * 128) / 256, 256>>>(x0, A0, MROWS, 1);
    k_split<<<(1536 * 128) / 256, 256>>>(W_ih, Wih2, 1536, 0);
    // 2: init h planes + barrier counters
    k_init<<<520, 256>>>();
    // 3: gx = x0 @ W_ih^T + b_ih   [32768 x 1536]
    k_mma_gemm<<<256 * 12, 256, GEMM_SMEM>>>(A0, Wih2, b_ih, gx, 1536, 12, 0);
    // 4: head fold (independent)
    k_prep1<<<14, 256>>>(W_half, W_out);
    // 5: GRU scan (PROFILED)
    k_scan<<<128, 256, SCAN_SMEM_BYTES>>>(W_hh, b_hh);
    // 6: head fold part 2
    k_prep2<<<1, 256>>>(W_out, b_half, b_out);
    // 7-9: FFN weight splits
    k_split<<<(512 * 128) / 256, 256>>>(W1, W12, 512, 0);
    k_split<<<(512 * 128) / 256, 256>>>(W2, W22, 512, 0);
    k_split<<<(512 * 128) / 256, 256>>>(W3, W32, 512, 0);
    // 10-12: FFN
    k_mma_gemm<<<256 * 4, 256, GEMM_SMEM>>>(e2,  W12, bb1, x1b, 512, 4, 1);
    k_mma_gemm<<<256 * 4, 256, GEMM_SMEM>>>(x1b, W22, bb2, x2b, 512, 4, 1);
    k_mma_gemm<<<256 * 4, 256, GEMM_SMEM>>>(x2b, W32, bb3, x3,  512, 4, 0);
    // 13: fused log_softmax + combined classifier head
    k_final<<<MROWS / 8, 256>>>(x3, out);
}